// round 1
// baseline (speedup 1.0000x reference)
#include <cuda_runtime.h>
#include <cuda_bf16.h>
#include <math.h>

// Problem constants
#define B_   8
#define DTOT 512
#define L_   2048
#define H_   8
#define M_   1024
#define DD   64            // head dim d
#define N_   (B_ * L_)     // 16384 rows per head

// Output layout (flattened fp32 concat of (z_q, vq_loss, indices, new_codebooks))
#define OUT_ZQ   0
#define ZQ_ELEMS (B_ * DTOT * L_)           // 8388608
#define OUT_LOSS (ZQ_ELEMS)                 // 8388608 (1 elem)
#define OUT_IDX  (ZQ_ELEMS + 1)             // 8388609
#define IDX_ELEMS (B_ * H_ * L_)            // 131072
#define OUT_NCB  (OUT_IDX + IDX_ELEMS)      // 8519681
#define NCB_ELEMS (H_ * M_ * DD)            // 524288

#define EPS_RMS 1.1920929e-07f
#define COS_EPS 1e-8f
#define DECAY   0.99f

// Scratch (no allocations allowed -> __device__ globals)
__device__ float g_sums[H_ * M_ * DD];   // segment sums  [H,M,d]
__device__ float g_counts[H_ * M_];      // segment counts [H,M]
__device__ float g_loss;                 // sum of (z - z_q)^2

// ---------------------------------------------------------------------------
// Kernel 0: zero scratch accumulators (graph replays must start clean)
// ---------------------------------------------------------------------------
__global__ void vq_zero_kernel() {
    int i = blockIdx.x * blockDim.x + threadIdx.x;
    if (i < H_ * M_ * DD) g_sums[i] = 0.0f;
    int j = i - H_ * M_ * DD;
    if (j >= 0 && j < H_ * M_) g_counts[j] = 0.0f;
    if (i == H_ * M_ * DD + H_ * M_) g_loss = 0.0f;
}

// ---------------------------------------------------------------------------
// Kernel 1: per-tile argmax over codebook + fused epilogue
//   grid = H_ * 256 blocks (each block: one head, 64 consecutive n)
//   block = 256 threads, 4x4 register blocking over (n, m)
// ---------------------------------------------------------------------------
__global__ __launch_bounds__(256, 4)
void vq_main_kernel(const float* __restrict__ z,
                    const float* __restrict__ cbk,
                    float* __restrict__ out) {
    __shared__ float Zs[64 * 64];          // [k][n]  (k-major, stride 64)
    __shared__ float Cs[64 * 66];          // [k][m]  (stride 66 -> conflict-free STS)
    __shared__ int   sidx[64];

    const int tid = threadIdx.x;
    const int tx = tid & 15;               // n-group (4 n each)
    const int ty = tid >> 4;               // m-group (4 m each, per chunk)

    const int tile = blockIdx.x;
    const int h  = tile >> 8;              // head
    const int t2 = tile & 255;
    const int n0 = t2 << 6;                // within-head row offset (64 rows)
    const int b  = n0 >> 11;               // n = b*L + l ; tile never crosses b
    const int l0 = n0 & 2047;

    // ---- load Z tile: Zs[j][li] = z[b, h*64+j, l0+li] ----
    {
        const float* zbase = z + ((b * DTOT + h * DD) * L_ + l0);
        #pragma unroll
        for (int i = 0; i < 4; i++) {
            int s = tid + i * 256;          // 1024 float4 slots
            int j = s >> 4;
            int c = (s & 15) << 2;
            float4 v = *(const float4*)(zbase + j * L_ + c);
            *(float4*)&Zs[j * 64 + c] = v;
        }
    }

    float best[4] = {-3.4e38f, -3.4e38f, -3.4e38f, -3.4e38f};
    int   bidx[4] = {0, 0, 0, 0};

    for (int mc = 0; mc < 16; mc++) {
        __syncthreads();
        // ---- load codebook chunk transposed: Cs[k][mm] = cbk[h, mc*64+mm, k] ----
        {
            int mm = tid >> 2;
            int kq = tid & 3;
            const float* src = cbk + ((h * M_ + (mc << 6) + mm) << 6) + (kq << 2);
            #pragma unroll
            for (int i = 0; i < 4; i++) {
                float4 v = *(const float4*)(src + (i << 4));
                int k0 = (kq << 2) + (i << 4);
                Cs[(k0 + 0) * 66 + mm] = v.x;
                Cs[(k0 + 1) * 66 + mm] = v.y;
                Cs[(k0 + 2) * 66 + mm] = v.z;
                Cs[(k0 + 3) * 66 + mm] = v.w;
            }
        }
        __syncthreads();

        float acc[4][4];
        #pragma unroll
        for (int i = 0; i < 4; i++)
            #pragma unroll
            for (int j = 0; j < 4; j++) acc[i][j] = 0.0f;

        const float* zp = Zs + (tx << 2);
        const float* cp = Cs + (ty << 2);
        #pragma unroll 8
        for (int k = 0; k < 64; k++) {
            float4 a  = *(const float4*)(zp + (k << 6));
            float2 c0 = *(const float2*)(cp + k * 66);
            float2 c1 = *(const float2*)(cp + k * 66 + 2);
            float aa[4] = {a.x, a.y, a.z, a.w};
            float bb[4] = {c0.x, c0.y, c1.x, c1.y};
            #pragma unroll
            for (int i = 0; i < 4; i++)
                #pragma unroll
                for (int j = 0; j < 4; j++)
                    acc[i][j] = fmaf(aa[i], bb[j], acc[i][j]);
        }

        // streaming argmax, m ascending within thread -> strict '>' keeps first idx
        int mbase = (mc << 6) + (ty << 2);
        #pragma unroll
        for (int j = 0; j < 4; j++) {
            #pragma unroll
            for (int i = 0; i < 4; i++) {
                if (acc[i][j] > best[i]) { best[i] = acc[i][j]; bidx[i] = mbase + j; }
            }
        }
    }

    // ---- cross-ty reduction (alias Cs) ----
    float* redV = Cs;                   // 16*64 floats
    int*   redI = (int*)(Cs + 1024);    // 16*64 ints
    __syncthreads();
    #pragma unroll
    for (int i = 0; i < 4; i++) {
        redV[ty * 64 + (tx << 2) + i] = best[i];
        redI[ty * 64 + (tx << 2) + i] = bidx[i];
    }
    __syncthreads();

    if (tid < 64) {
        int n = tid;
        float bv = redV[n];
        int   bi = redI[n];
        #pragma unroll
        for (int t = 1; t < 16; t++) {
            float v = redV[t * 64 + n];
            int   iv = redI[t * 64 + n];
            if (v > bv || (v == bv && iv < bi)) { bv = v; bi = iv; }
        }
        sidx[n] = bi;
        // indices_out[b, h, l]  (written as float)
        out[OUT_IDX + (b * H_ + h) * L_ + l0 + n] = (float)bi;
        atomicAdd(&g_counts[h * M_ + bi], 1.0f);
    }
    __syncthreads();

    // ---- epilogue: z_q writeback, segment sums, loss ----
    {
        int nn = tid & 63;            // column within tile
        int ks = tid >> 6;            // k-subset: handles k = ks*16 .. ks*16+15
        int ci = sidx[nn];
        const float* cw = cbk + ((h * M_ + ci) << 6);
        float* srow = &g_sums[(h * M_ + ci) << 6];
        float lsum = 0.0f;
        #pragma unroll
        for (int t = 0; t < 16; t++) {
            int k = (ks << 4) + t;
            float q  = cw[k];
            float zv = Zs[k * 64 + nn];
            float dd = zv - q;
            lsum = fmaf(dd, dd, lsum);
            out[OUT_ZQ + (b * DTOT + h * DD + k) * L_ + l0 + nn] = q;
            atomicAdd(&srow[k], zv);
        }
        #pragma unroll
        for (int o = 16; o > 0; o >>= 1)
            lsum += __shfl_down_sync(0xffffffffu, lsum, o);
        if ((tid & 31) == 0) atomicAdd(&g_loss, lsum);
    }
}

// ---------------------------------------------------------------------------
// Kernel 2: finalize — means -> slerp -> rms_norm -> new_codebooks; loss scalar
//   1024 blocks x 256 threads; one warp per (h,m) row, 2 dims per lane
// ---------------------------------------------------------------------------
__global__ __launch_bounds__(256)
void vq_final_kernel(const float* __restrict__ cbk, float* __restrict__ out) {
    const int tid  = threadIdx.x;
    const int warp = tid >> 5;
    const int lane = tid & 31;
    const int r = blockIdx.x * 8 + warp;    // row index in [0, H_*M_)
    const int j0 = lane * 2;

    if (blockIdx.x == 0 && tid == 0) {
        out[OUT_LOSS] = g_loss * (1.25f / (float)ZQ_ELEMS);
    }

    float hi0 = cbk[r * DD + j0];
    float hi1 = cbk[r * DD + j0 + 1];
    float cnt = g_counts[r];
    float* orow = out + OUT_NCB + r * DD;

    if (cnt <= 0.0f) {
        orow[j0]     = hi0;
        orow[j0 + 1] = hi1;
        return;
    }

    float inv = 1.0f / fmaxf(cnt, 1.0f);
    float lo0 = g_sums[r * DD + j0]     * inv;
    float lo1 = g_sums[r * DD + j0 + 1] * inv;

    float dot = lo0 * hi0 + lo1 * hi1;
    float nl2 = lo0 * lo0 + lo1 * lo1;
    float nh2 = hi0 * hi0 + hi1 * hi1;
    #pragma unroll
    for (int o = 16; o > 0; o >>= 1) {
        dot += __shfl_xor_sync(0xffffffffu, dot, o);
        nl2 += __shfl_xor_sync(0xffffffffu, nl2, o);
        nh2 += __shfl_xor_sync(0xffffffffu, nh2, o);
    }

    float cosv = dot / fmaxf(sqrtf(nl2) * sqrtf(nh2), COS_EPS);
    cosv = fminf(fmaxf(cosv, -1.0f + 1e-7f), 1.0f - 1e-7f);
    float omega = acosf(cosv);
    float so = sinf(omega);
    float sa = sinf((1.0f - DECAY) * omega);
    float sb = sinf(DECAY * omega);

    float o0 = (lo0 * sa + hi0 * sb) / so;
    float o1 = (lo1 * sa + hi1 * sb) / so;

    float ss = o0 * o0 + o1 * o1;
    #pragma unroll
    for (int o = 16; o > 0; o >>= 1)
        ss += __shfl_xor_sync(0xffffffffu, ss, o);

    float denom = sqrtf(ss * (1.0f / (float)DD) + EPS_RMS);
    orow[j0]     = o0 / denom;
    orow[j0 + 1] = o1 / denom;
}

// ---------------------------------------------------------------------------
extern "C" void kernel_launch(void* const* d_in, const int* in_sizes, int n_in,
                              void* d_out, int out_size) {
    const float* z   = (const float*)d_in[0];
    const float* cbk = (const float*)d_in[1];
    float* out = (float*)d_out;

    int zero_total = H_ * M_ * DD + H_ * M_ + 1;
    vq_zero_kernel<<<(zero_total + 255) / 256, 256>>>();
    vq_main_kernel<<<H_ * 256, 256>>>(z, cbk, out);
    vq_final_kernel<<<H_ * M_ / 8, 256>>>(cbk, out);
}